// round 1
// baseline (speedup 1.0000x reference)
#include <cuda_runtime.h>

// DiffusionGraphConv — GB300 sm_103a
// Pipeline:
//   1) CSR build per support (histogram / scan / scatter)      ~10us
//   2) X0[n][b][f] = concat(inputs, state) transposed copy     ~20us
//   3) Wp fold: absorbs Chebyshev "2*" and "-x0" into weights  ~2us
//   4) SpMM x4 (gather form, one CTA per dest row)             ~420us (L2-bound)
//   5) out = sum_m X[m] @ Wp[m] + bias  (fp32 SGEMM)           ~600us (FFMA-bound)

#define NB 4096
#define BB 32
#define DD 64
#define HH 64
#define FF 128
#define EE 65536
#define SS 2
#define MM 5
#define OO 128
#define ROWLEN (BB * FF)        // 4096 floats / node-row
#define ROWLEN4 (ROWLEN / 4)    // 1024 float4

// ---- device scratch (allocation-free contract: __device__ globals) ----
__device__ float  g_X[(size_t)MM * NB * ROWLEN];   // 5 x 64MB = 320MB
__device__ float2 g_edges[SS * EE];                // (col_as_bits, val), row-sorted
__device__ int    g_off[SS * (NB + 1)];
__device__ int    g_cur[SS * NB];
__device__ int    g_cnt[SS * NB];
__device__ float  g_Wp[MM * FF * OO];              // folded weights [m][f][o]

// ---------------- CSR build ----------------
__global__ void k_zero_cnt() {
    int i = blockIdx.x * blockDim.x + threadIdx.x;
    if (i < SS * NB) g_cnt[i] = 0;
}

__global__ void k_histo(const int* __restrict__ rows) {
    int i = blockIdx.x * blockDim.x + threadIdx.x;   // [0, S*E)
    int s = i >> 16;                                  // E = 65536
    atomicAdd(&g_cnt[s * NB + rows[i]], 1);
}

// one block per support: exclusive scan of 4096 counts (1024 thr x 4 items)
__global__ void k_scan() {
    int s = blockIdx.x;
    int t = threadIdx.x;
    __shared__ int wsum[32];
    int base = s * NB + t * 4;
    int v0 = g_cnt[base + 0], v1 = g_cnt[base + 1];
    int v2 = g_cnt[base + 2], v3 = g_cnt[base + 3];
    int tot = v0 + v1 + v2 + v3;
    int lane = t & 31, w = t >> 5;
    int x = tot;
#pragma unroll
    for (int d = 1; d < 32; d <<= 1) {
        int y = __shfl_up_sync(0xffffffffu, x, d);
        if (lane >= d) x += y;
    }
    if (lane == 31) wsum[w] = x;
    __syncthreads();
    if (w == 0) {
        int y = wsum[lane];
#pragma unroll
        for (int d = 1; d < 32; d <<= 1) {
            int z = __shfl_up_sync(0xffffffffu, y, d);
            if (lane >= d) y += z;
        }
        wsum[lane] = y;
    }
    __syncthreads();
    int excl = x - tot + (w > 0 ? wsum[w - 1] : 0);
    int ob = s * (NB + 1) + t * 4;
    g_off[ob + 0] = excl;
    g_off[ob + 1] = excl + v0;
    g_off[ob + 2] = excl + v0 + v1;
    g_off[ob + 3] = excl + v0 + v1 + v2;
    g_cur[base + 0] = excl;
    g_cur[base + 1] = excl + v0;
    g_cur[base + 2] = excl + v0 + v1;
    g_cur[base + 3] = excl + v0 + v1 + v2;
    if (t == 1023) g_off[s * (NB + 1) + NB] = excl + tot;
}

__global__ void k_scatter(const int* __restrict__ rows,
                          const int* __restrict__ cols,
                          const float* __restrict__ vals) {
    int i = blockIdx.x * blockDim.x + threadIdx.x;
    int s = i >> 16;
    int r = rows[i];
    int p = atomicAdd(&g_cur[s * NB + r], 1);
    g_edges[s * EE + p] = make_float2(__int_as_float(cols[i]), vals[i]);
}

// ---------------- X0 build: X0[n][b][f] = concat(inputs,state)[b][n][f] ----------------
__global__ void k_build(const float4* __restrict__ in, const float4* __restrict__ st) {
    int tid = blockIdx.x * blockDim.x + threadIdx.x;  // N*B*32
    int q = tid & 31;
    int b = (tid >> 5) & 31;
    int n = tid >> 10;
    float4 v;
    if (q < 16)
        v = in[(size_t)b * (NB * DD / 4) + n * (DD / 4) + q];
    else
        v = st[(size_t)b * (NB * HH / 4) + n * (HH / 4) + (q - 16)];
    ((float4*)g_X)[(size_t)n * ROWLEN4 + b * (FF / 4) + q] = v;
}

// ---------------- weight fold ----------------
// out = X0*(W0 - W2 - W4) + Y0*W1 + Z0*(2W2) + Y1*W3 + Z1*(2W4)
// weight layout: [f*M + m][o];  g_Wp layout: [m][f][o]
__global__ void k_wprep(const float* __restrict__ w) {
    int i = blockIdx.x * blockDim.x + threadIdx.x;  // FF*OO
    int f = i >> 7;
    int o = i & 127;
    float w0 = w[(f * MM + 0) * OO + o];
    float w1 = w[(f * MM + 1) * OO + o];
    float w2 = w[(f * MM + 2) * OO + o];
    float w3 = w[(f * MM + 3) * OO + o];
    float w4 = w[(f * MM + 4) * OO + o];
    g_Wp[(0 * FF + f) * OO + o] = w0 - w2 - w4;
    g_Wp[(1 * FF + f) * OO + o] = w1;
    g_Wp[(2 * FF + f) * OO + o] = 2.f * w2;
    g_Wp[(3 * FF + f) * OO + o] = w3;
    g_Wp[(4 * FF + f) * OO + o] = 2.f * w4;
}

// ---------------- SpMM (gather): dst[n] = sum_e val * src[col] ----------------
// stage 0: Y_s = A_s X0   (dst m = 1+2s, src m = 0)
// stage 1: Z_s = A_s Y_s  (dst m = 2+2s, src m = 1+2s)
__global__ void __launch_bounds__(256) k_spmm(int stage) {
    int n = blockIdx.x, s = blockIdx.y, t = threadIdx.x;
    const float4* src = (const float4*)g_X +
        (stage == 0 ? (size_t)0 : (size_t)(1 + 2 * s) * NB * ROWLEN4);
    float4* dst = (float4*)g_X + (size_t)(stage + 1 + 2 * s) * NB * ROWLEN4 +
                  (size_t)n * ROWLEN4;
    int e   = g_off[s * (NB + 1) + n];
    int end = g_off[s * (NB + 1) + n + 1];
    const float2* ep = g_edges + s * EE;
    float4 a0 = make_float4(0.f, 0.f, 0.f, 0.f);
    float4 a1 = a0, a2 = a0, a3 = a0;
    for (; e < end; e++) {
        float2 cv = ep[e];
        int c   = __float_as_int(cv.x);
        float v = cv.y;
        const float4* r = src + (size_t)c * ROWLEN4;
        float4 b0 = r[t], b1 = r[t + 256], b2 = r[t + 512], b3 = r[t + 768];
        a0.x = fmaf(v, b0.x, a0.x); a0.y = fmaf(v, b0.y, a0.y);
        a0.z = fmaf(v, b0.z, a0.z); a0.w = fmaf(v, b0.w, a0.w);
        a1.x = fmaf(v, b1.x, a1.x); a1.y = fmaf(v, b1.y, a1.y);
        a1.z = fmaf(v, b1.z, a1.z); a1.w = fmaf(v, b1.w, a1.w);
        a2.x = fmaf(v, b2.x, a2.x); a2.y = fmaf(v, b2.y, a2.y);
        a2.z = fmaf(v, b2.z, a2.z); a2.w = fmaf(v, b2.w, a2.w);
        a3.x = fmaf(v, b3.x, a3.x); a3.y = fmaf(v, b3.y, a3.y);
        a3.z = fmaf(v, b3.z, a3.z); a3.w = fmaf(v, b3.w, a3.w);
    }
    dst[t] = a0; dst[t + 256] = a1; dst[t + 512] = a2; dst[t + 768] = a3;
}

// ---------------- final GEMM: out[bn][o] = sum_m sum_f X[m][n][b][f]*Wp[m][f][o] + bias ----------------
#define BM 128
#define BN 128
#define BK 16

__global__ void __launch_bounds__(256) k_gemm(const float* __restrict__ biases,
                                              float* __restrict__ out) {
    __shared__ float As[BK][BM + 4];   // +4 keeps float4 alignment, breaks conflicts
    __shared__ float Ws[BK][BN];
    int t = threadIdx.x;
    int bn0 = blockIdx.x * BM;
    int n0 = bn0 & (NB - 1);
    int b  = bn0 >> 12;               // N = 4096 = 2^12, so one b per 128-row tile
    int ty = t >> 4, tx = t & 15;

    float acc[8][8];
#pragma unroll
    for (int i = 0; i < 8; i++)
#pragma unroll
        for (int j = 0; j < 8; j++) acc[i][j] = 0.f;

    for (int kt = 0; kt < (MM * FF) / BK; kt++) {   // 40 k-tiles
        int m  = kt >> 3;              // 128/16 = 8 tiles per m
        int f0 = (kt & 7) * BK;
        // A tile: 128 rows x 16 k, 2 float4 per thread, stored transposed
#pragma unroll
        for (int i = 0; i < 2; i++) {
            int li  = t + i * 256;
            int row = li >> 2;
            int fq  = (li & 3) * 4;
            const float* gp = g_X + ((size_t)m * NB + (n0 + row)) * ROWLEN +
                              b * FF + f0 + fq;
            float4 v = *(const float4*)gp;
            As[fq + 0][row] = v.x; As[fq + 1][row] = v.y;
            As[fq + 2][row] = v.z; As[fq + 3][row] = v.w;
        }
        // W tile: 16 k x 128 o
#pragma unroll
        for (int i = 0; i < 2; i++) {
            int li = t + i * 256;
            int f  = li >> 5;
            int oq = (li & 31) * 4;
            float4 v = *(const float4*)(g_Wp + ((size_t)m * FF + f0 + f) * OO + oq);
            *(float4*)&Ws[f][oq] = v;
        }
        __syncthreads();
#pragma unroll
        for (int kk = 0; kk < BK; kk++) {
            float a[8], w[8];
            *(float4*)(a + 0) = *(const float4*)&As[kk][ty * 8 + 0];
            *(float4*)(a + 4) = *(const float4*)&As[kk][ty * 8 + 4];
            *(float4*)(w + 0) = *(const float4*)&Ws[kk][tx * 8 + 0];
            *(float4*)(w + 4) = *(const float4*)&Ws[kk][tx * 8 + 4];
#pragma unroll
            for (int i = 0; i < 8; i++)
#pragma unroll
                for (int j = 0; j < 8; j++)
                    acc[i][j] = fmaf(a[i], w[j], acc[i][j]);
        }
        __syncthreads();
    }

    float bias[8];
    *(float4*)(bias + 0) = *(const float4*)(biases + tx * 8 + 0);
    *(float4*)(bias + 4) = *(const float4*)(biases + tx * 8 + 4);
#pragma unroll
    for (int i = 0; i < 8; i++) {
        size_t ro = (size_t)(bn0 + ty * 8 + i) * OO + tx * 8;
        float4 o0 = make_float4(acc[i][0] + bias[0], acc[i][1] + bias[1],
                                acc[i][2] + bias[2], acc[i][3] + bias[3]);
        float4 o1 = make_float4(acc[i][4] + bias[4], acc[i][5] + bias[5],
                                acc[i][6] + bias[6], acc[i][7] + bias[7]);
        *(float4*)(out + ro)     = o0;
        *(float4*)(out + ro + 4) = o1;
    }
}

// ---------------- launch ----------------
extern "C" void kernel_launch(void* const* d_in, const int* in_sizes, int n_in,
                              void* d_out, int out_size) {
    const float* inputs = (const float*)d_in[0];
    const float* state  = (const float*)d_in[1];
    const int*   rows   = (const int*)d_in[2];
    const int*   cols   = (const int*)d_in[3];
    const float* vals   = (const float*)d_in[4];
    const float* weight = (const float*)d_in[5];
    const float* biases = (const float*)d_in[6];
    float* out = (float*)d_out;
    (void)in_sizes; (void)n_in; (void)out_size;

    k_zero_cnt<<<(SS * NB + 255) / 256, 256>>>();
    k_histo<<<(SS * EE) / 256, 256>>>(rows);
    k_scan<<<SS, 1024>>>();
    k_scatter<<<(SS * EE) / 256, 256>>>(rows, cols, vals);
    k_build<<<(NB * BB * 32) / 256, 256>>>((const float4*)inputs,
                                           (const float4*)state);
    k_wprep<<<(FF * OO) / 256, 256>>>(weight);
    k_spmm<<<dim3(NB, SS), 256>>>(0);   // Y_s = A_s X0
    k_spmm<<<dim3(NB, SS), 256>>>(1);   // Z_s = A_s Y_s
    k_gemm<<<(BB * NB) / BM, 256>>>(biases, out);
}

// round 3
// speedup vs baseline: 1.3675x; 1.3675x over previous
#include <cuda_runtime.h>
#include <cuda_bf16.h>
#include <cstdint>

// DiffusionGraphConv — GB300 sm_103 (baseline PTX only; no tcgen05 in this toolchain)
//   1) CSR build per support                                    ~10us
//   2) X0[n][b][f] = concat(inputs,state) transposed copy       ~20us
//   3) Wp fold + transpose + bf16 hi/lo split                   ~3us
//   4) SpMM x4 (gather form, one CTA per dest row)              ~340us (L2-bound)
//   5) out = sum_m X[m] @ Wp[m] + bias  via mma.sync bf16x3     ~120us (HMMA)

#define NB 4096
#define BB 32
#define DD 64
#define HH 64
#define FF 128
#define EE 65536
#define SS 2
#define MM 5
#define OO 128
#define ROWLEN (BB * FF)
#define ROWLEN4 (ROWLEN / 4)

// ---- device scratch ----
__device__ float  g_X[(size_t)MM * NB * ROWLEN];   // 320MB
__device__ float2 g_edges[SS * EE];
__device__ int    g_off[SS * (NB + 1)];
__device__ int    g_cur[SS * NB];
__device__ int    g_cnt[SS * NB];
__device__ __nv_bfloat16 g_Wth[MM * OO * FF];      // folded, transposed [m][o][f], hi
__device__ __nv_bfloat16 g_Wtl[MM * OO * FF];      // lo

// ---------------- CSR build ----------------
__global__ void k_zero_cnt() {
    int i = blockIdx.x * blockDim.x + threadIdx.x;
    if (i < SS * NB) g_cnt[i] = 0;
}
__global__ void k_histo(const int* __restrict__ rows) {
    int i = blockIdx.x * blockDim.x + threadIdx.x;
    int s = i >> 16;
    atomicAdd(&g_cnt[s * NB + rows[i]], 1);
}
__global__ void k_scan() {
    int s = blockIdx.x;
    int t = threadIdx.x;
    __shared__ int wsum[32];
    int base = s * NB + t * 4;
    int v0 = g_cnt[base + 0], v1 = g_cnt[base + 1];
    int v2 = g_cnt[base + 2], v3 = g_cnt[base + 3];
    int tot = v0 + v1 + v2 + v3;
    int lane = t & 31, w = t >> 5;
    int x = tot;
#pragma unroll
    for (int d = 1; d < 32; d <<= 1) {
        int y = __shfl_up_sync(0xffffffffu, x, d);
        if (lane >= d) x += y;
    }
    if (lane == 31) wsum[w] = x;
    __syncthreads();
    if (w == 0) {
        int y = wsum[lane];
#pragma unroll
        for (int d = 1; d < 32; d <<= 1) {
            int z = __shfl_up_sync(0xffffffffu, y, d);
            if (lane >= d) y += z;
        }
        wsum[lane] = y;
    }
    __syncthreads();
    int excl = x - tot + (w > 0 ? wsum[w - 1] : 0);
    int ob = s * (NB + 1) + t * 4;
    g_off[ob + 0] = excl;
    g_off[ob + 1] = excl + v0;
    g_off[ob + 2] = excl + v0 + v1;
    g_off[ob + 3] = excl + v0 + v1 + v2;
    g_cur[base + 0] = excl;
    g_cur[base + 1] = excl + v0;
    g_cur[base + 2] = excl + v0 + v1;
    g_cur[base + 3] = excl + v0 + v1 + v2;
    if (t == 1023) g_off[s * (NB + 1) + NB] = excl + tot;
}
__global__ void k_scatter(const int* __restrict__ rows, const int* __restrict__ cols,
                          const float* __restrict__ vals) {
    int i = blockIdx.x * blockDim.x + threadIdx.x;
    int s = i >> 16;
    int r = rows[i];
    int p = atomicAdd(&g_cur[s * NB + r], 1);
    g_edges[s * EE + p] = make_float2(__int_as_float(cols[i]), vals[i]);
}

// ---------------- X0 build ----------------
__global__ void k_build(const float4* __restrict__ in, const float4* __restrict__ st) {
    int tid = blockIdx.x * blockDim.x + threadIdx.x;
    int q = tid & 31;
    int b = (tid >> 5) & 31;
    int n = tid >> 10;
    float4 v;
    if (q < 16)
        v = in[(size_t)b * (NB * DD / 4) + n * (DD / 4) + q];
    else
        v = st[(size_t)b * (NB * HH / 4) + n * (HH / 4) + (q - 16)];
    ((float4*)g_X)[(size_t)n * ROWLEN4 + b * (FF / 4) + q] = v;
}

// ---------------- weight fold + transpose + bf16 split ----------------
// out = X0*(W0-W2-W4) + Y0*W1 + Z0*2W2 + Y1*W3 + Z1*2W4
__global__ void k_wprep(const float* __restrict__ w) {
    int i = blockIdx.x * blockDim.x + threadIdx.x;  // FF*OO
    int f = i & 127;
    int o = i >> 7;
    float w0 = w[(f * MM + 0) * OO + o];
    float w1 = w[(f * MM + 1) * OO + o];
    float w2 = w[(f * MM + 2) * OO + o];
    float w3 = w[(f * MM + 3) * OO + o];
    float w4 = w[(f * MM + 4) * OO + o];
    float p[5] = {w0 - w2 - w4, w1, 2.f * w2, w3, 2.f * w4};
#pragma unroll
    for (int m = 0; m < MM; m++) {
        __nv_bfloat16 hi = __float2bfloat16_rn(p[m]);
        float lo = p[m] - __bfloat162float(hi);
        size_t idx = ((size_t)m * OO + o) * FF + f;
        g_Wth[idx] = hi;
        g_Wtl[idx] = __float2bfloat16_rn(lo);
    }
}

// ---------------- SpMM (gather) ----------------
__global__ void __launch_bounds__(256) k_spmm(int stage) {
    int n = blockIdx.x, s = blockIdx.y, t = threadIdx.x;
    const float4* src = (const float4*)g_X +
        (stage == 0 ? (size_t)0 : (size_t)(1 + 2 * s) * NB * ROWLEN4);
    float4* dst = (float4*)g_X + (size_t)(stage + 1 + 2 * s) * NB * ROWLEN4 +
                  (size_t)n * ROWLEN4;
    int e   = g_off[s * (NB + 1) + n];
    int end = g_off[s * (NB + 1) + n + 1];
    const float2* ep = g_edges + s * EE;
    float4 a0 = make_float4(0.f, 0.f, 0.f, 0.f);
    float4 a1 = a0, a2 = a0, a3 = a0;
    for (; e < end; e++) {
        float2 cv = ep[e];
        int c   = __float_as_int(cv.x);
        float v = cv.y;
        const float4* r = src + (size_t)c * ROWLEN4;
        float4 b0 = r[t], b1 = r[t + 256], b2 = r[t + 512], b3 = r[t + 768];
        a0.x = fmaf(v, b0.x, a0.x); a0.y = fmaf(v, b0.y, a0.y);
        a0.z = fmaf(v, b0.z, a0.z); a0.w = fmaf(v, b0.w, a0.w);
        a1.x = fmaf(v, b1.x, a1.x); a1.y = fmaf(v, b1.y, a1.y);
        a1.z = fmaf(v, b1.z, a1.z); a1.w = fmaf(v, b1.w, a1.w);
        a2.x = fmaf(v, b2.x, a2.x); a2.y = fmaf(v, b2.y, a2.y);
        a2.z = fmaf(v, b2.z, a2.z); a2.w = fmaf(v, b2.w, a2.w);
        a3.x = fmaf(v, b3.x, a3.x); a3.y = fmaf(v, b3.y, a3.y);
        a3.z = fmaf(v, b3.z, a3.z); a3.w = fmaf(v, b3.w, a3.w);
    }
    dst[t] = a0; dst[t + 256] = a1; dst[t + 512] = a2; dst[t + 768] = a3;
}

// ---------------- mma.sync bf16x3 GEMM ----------------
// D[bn][o] = sum_{m,f} X[m][n][b][f]*Wp[m][f][o] + bias
// CTA tile 128x128, K=640 in 20 tiles of BK=32, double-buffered smem.
// 8 warps in 2(m) x 4(n): each warp 64x32 via m16n8k16, bf16 hi/lo x3 MMAs.
#define BK   32
#define BKP  40                      // padded row (uint16 units) — conflict-free frags
#define TSZ  (128 * BKP)             // one operand tile, uint16 units (5120)
#define STG  (4 * TSZ)               // Ah,Al,Bh,Bl per stage (20480 u16 = 40KB)
#define GEMM_SMEM (2 * STG * 2)      // bytes = 81920

__device__ __forceinline__ void mma_bf16(float* c, const uint32_t* a, const uint32_t* b) {
    asm volatile(
        "mma.sync.aligned.m16n8k16.row.col.f32.bf16.bf16.f32 "
        "{%0,%1,%2,%3}, {%4,%5,%6,%7}, {%8,%9}, {%0,%1,%2,%3};\n"
        : "+f"(c[0]), "+f"(c[1]), "+f"(c[2]), "+f"(c[3])
        : "r"(a[0]), "r"(a[1]), "r"(a[2]), "r"(a[3]), "r"(b[0]), "r"(b[1]));
}

__global__ void __launch_bounds__(256) k_gemm_mma(const float* __restrict__ biases,
                                                  float* __restrict__ out) {
    extern __shared__ uint16_t smx[];   // [2][Ah|Al|Bh|Bl][128][BKP]

    const int t = threadIdx.x;
    const int wid = t >> 5, lane = t & 31;
    const int qr = lane >> 2, qc = lane & 3;
    const int wm = wid & 1, wn = wid >> 1;

    const int bn0 = blockIdx.x * 128;
    const int n0 = bn0 & (NB - 1);
    const int b  = bn0 >> 12;

    // global load roles
    const int ar = t >> 1, ah = t & 1;   // A: row, 16-float half
    const int bo = t & 127, bp = t >> 7; // B: o row, 16-bf16 part

    float acc[4][4][4];
#pragma unroll
    for (int i = 0; i < 4; i++)
#pragma unroll
        for (int j = 0; j < 4; j++)
#pragma unroll
            for (int k = 0; k < 4; k++) acc[i][j][k] = 0.f;

    float4 aReg[4];
    uint4  bRegH[2], bRegL[2];

#define LDG_TILE(kt)                                                              \
    {                                                                             \
        const int m_ = (kt) >> 2, f0_ = ((kt) & 3) * BK;                          \
        const float4* ap = (const float4*)(g_X +                                  \
            (((size_t)m_ * NB + (n0 + ar)) * BB + b) * FF + f0_ + ah * 16);       \
        aReg[0] = ap[0]; aReg[1] = ap[1]; aReg[2] = ap[2]; aReg[3] = ap[3];       \
        const uint4* bh = (const uint4*)(g_Wth + ((size_t)m_ * OO + bo) * FF +    \
                                         f0_ + bp * 16);                          \
        const uint4* bl = (const uint4*)(g_Wtl + ((size_t)m_ * OO + bo) * FF +    \
                                         f0_ + bp * 16);                          \
        bRegH[0] = bh[0]; bRegH[1] = bh[1];                                       \
        bRegL[0] = bl[0]; bRegL[1] = bl[1];                                       \
    }

#define STS_TILE(st)                                                              \
    {                                                                             \
        uint16_t* Ah = smx + (st) * STG;                                          \
        uint16_t* Al = Ah + TSZ;                                                  \
        uint16_t* Bh = Ah + 2 * TSZ;                                              \
        uint16_t* Bl = Ah + 3 * TSZ;                                              \
        const float* av = (const float*)aReg;                                     \
        uint32_t* AhR = (uint32_t*)(Ah + ar * BKP + ah * 16);                     \
        uint32_t* AlR = (uint32_t*)(Al + ar * BKP + ah * 16);                     \
        _Pragma("unroll")                                                         \
        for (int j = 0; j < 8; j++) {                                             \
            float x0 = av[2 * j], x1 = av[2 * j + 1];                             \
            __nv_bfloat16 h0 = __float2bfloat16_rn(x0);                           \
            __nv_bfloat16 h1 = __float2bfloat16_rn(x1);                           \
            __nv_bfloat16 l0 = __float2bfloat16_rn(x0 - __bfloat162float(h0));    \
            __nv_bfloat16 l1 = __float2bfloat16_rn(x1 - __bfloat162float(h1));    \
            __nv_bfloat162 hp; hp.x = h0; hp.y = h1;                              \
            __nv_bfloat162 lp; lp.x = l0; lp.y = l1;                              \
            AhR[j] = *(uint32_t*)&hp;                                             \
            AlR[j] = *(uint32_t*)&lp;                                             \
        }                                                                         \
        uint32_t* BhR = (uint32_t*)(Bh + bo * BKP + bp * 16);                     \
        uint32_t* BlR = (uint32_t*)(Bl + bo * BKP + bp * 16);                     \
        const uint32_t* bhv = (const uint32_t*)bRegH;                             \
        const uint32_t* blv = (const uint32_t*)bRegL;                             \
        _Pragma("unroll")                                                         \
        for (int j = 0; j < 8; j++) { BhR[j] = bhv[j]; BlR[j] = blv[j]; }         \
    }

    LDG_TILE(0);
    STS_TILE(0);
    __syncthreads();

    for (int kt = 0; kt < 20; kt++) {
        const int st = kt & 1;
        if (kt < 19) LDG_TILE(kt + 1);

        const uint16_t* Ah = smx + st * STG;
        const uint16_t* Al = Ah + TSZ;
        const uint16_t* Bh = Ah + 2 * TSZ;
        const uint16_t* Bl = Ah + 3 * TSZ;

#pragma unroll
        for (int kk = 0; kk < BK; kk += 16) {
            uint32_t fbh[4][2], fbl[4][2];
#pragma unroll
            for (int ni = 0; ni < 4; ni++) {
                int nb = wn * 32 + ni * 8 + qr;
                int w0 = nb * BKP + kk + 2 * qc;
                fbh[ni][0] = *(const uint32_t*)&Bh[w0];
                fbh[ni][1] = *(const uint32_t*)&Bh[w0 + 8];
                fbl[ni][0] = *(const uint32_t*)&Bl[w0];
                fbl[ni][1] = *(const uint32_t*)&Bl[w0 + 8];
            }
#pragma unroll
            for (int mi = 0; mi < 4; mi++) {
                int rb = wm * 64 + mi * 16 + qr;
                int w0 = rb * BKP + kk + 2 * qc;
                uint32_t fah[4], fal[4];
                fah[0] = *(const uint32_t*)&Ah[w0];
                fah[1] = *(const uint32_t*)&Ah[w0 + 8 * BKP];
                fah[2] = *(const uint32_t*)&Ah[w0 + 8];
                fah[3] = *(const uint32_t*)&Ah[w0 + 8 * BKP + 8];
                fal[0] = *(const uint32_t*)&Al[w0];
                fal[1] = *(const uint32_t*)&Al[w0 + 8 * BKP];
                fal[2] = *(const uint32_t*)&Al[w0 + 8];
                fal[3] = *(const uint32_t*)&Al[w0 + 8 * BKP + 8];
#pragma unroll
                for (int ni = 0; ni < 4; ni++) {
                    mma_bf16(acc[mi][ni], fah, fbh[ni]);
                    mma_bf16(acc[mi][ni], fah, fbl[ni]);
                    mma_bf16(acc[mi][ni], fal, fbh[ni]);
                }
            }
        }

        if (kt < 19) {
            STS_TILE(1 - st);
        }
        __syncthreads();
    }

    // epilogue: D frag (m16n8): d0,d1 -> row qr, cols 2qc,2qc+1 ; d2,d3 -> row qr+8
#pragma unroll
    for (int mi = 0; mi < 4; mi++) {
#pragma unroll
        for (int ni = 0; ni < 4; ni++) {
            int col = wn * 32 + ni * 8 + 2 * qc;
            float b0 = biases[col], b1 = biases[col + 1];
            int r0 = bn0 + wm * 64 + mi * 16 + qr;
            float2 v0 = make_float2(acc[mi][ni][0] + b0, acc[mi][ni][1] + b1);
            float2 v1 = make_float2(acc[mi][ni][2] + b0, acc[mi][ni][3] + b1);
            *(float2*)(out + (size_t)r0 * OO + col)       = v0;
            *(float2*)(out + (size_t)(r0 + 8) * OO + col) = v1;
        }
    }
#undef LDG_TILE
#undef STS_TILE
}

// ---------------- launch ----------------
extern "C" void kernel_launch(void* const* d_in, const int* in_sizes, int n_in,
                              void* d_out, int out_size) {
    const float* inputs = (const float*)d_in[0];
    const float* state  = (const float*)d_in[1];
    const int*   rows   = (const int*)d_in[2];
    const int*   cols   = (const int*)d_in[3];
    const float* vals   = (const float*)d_in[4];
    const float* weight = (const float*)d_in[5];
    const float* biases = (const float*)d_in[6];
    float* out = (float*)d_out;
    (void)in_sizes; (void)n_in; (void)out_size;

    cudaFuncSetAttribute(k_gemm_mma, cudaFuncAttributeMaxDynamicSharedMemorySize,
                         GEMM_SMEM);

    k_zero_cnt<<<(SS * NB + 255) / 256, 256>>>();
    k_histo<<<(SS * EE) / 256, 256>>>(rows);
    k_scan<<<SS, 1024>>>();
    k_scatter<<<(SS * EE) / 256, 256>>>(rows, cols, vals);
    k_build<<<(NB * BB * 32) / 256, 256>>>((const float4*)inputs,
                                           (const float4*)state);
    k_wprep<<<(FF * OO) / 256, 256>>>(weight);
    k_spmm<<<dim3(NB, SS), 256>>>(0);
    k_spmm<<<dim3(NB, SS), 256>>>(1);
    k_gemm_mma<<<(BB * NB) / 128, 256, GEMM_SMEM>>>(biases, out);
}

// round 4
// speedup vs baseline: 1.5315x; 1.1199x over previous
#include <cuda_runtime.h>
#include <cuda_bf16.h>
#include <cuda_fp16.h>
#include <cstdint>

// DiffusionGraphConv — GB300 sm_103 (baseline PTX; no tcgen05 in this toolchain)
//   1) CSR build per support                                    ~10us
//   2) X0 build: fp32 [n][b][f] + fp16 mirror                   ~25us
//   3) Wp fold + transpose + bf16 hi/lo split                   ~3us
//   4) SpMM x4 over fp16 rows (gather, fp32 accum, fp16 out)    ~120us (L2/cvt)
//   5) out = X0@W0(fp32 src) + sum Xm@Wm(fp16 src), bf16x3 MMA  ~120us (HMMA)

#define NB 4096
#define BB 32
#define DD 64
#define HH 64
#define FF 128
#define EE 65536
#define SS 2
#define MM 5
#define OO 128
#define ROWLEN (BB * FF)        // 4096 elements per node-row
#define ROWLEN4 (ROWLEN / 4)

// ---- device scratch ----
__device__ float  g_X[(size_t)NB * ROWLEN];            // X0 fp32, 64MB (GEMM m=0)
__device__ __half g_Xh[(size_t)MM * NB * ROWLEN];      // [X0h,Y0,Z0,Y1,Z1] fp16, 160MB
__device__ float2 g_edges[SS * EE];
__device__ int    g_off[SS * (NB + 1)];
__device__ int    g_cur[SS * NB];
__device__ int    g_cnt[SS * NB];
__device__ __nv_bfloat16 g_Wth[MM * OO * FF];          // folded, transposed [m][o][f], hi
__device__ __nv_bfloat16 g_Wtl[MM * OO * FF];          // lo

// ---------------- CSR build ----------------
__global__ void k_zero_cnt() {
    int i = blockIdx.x * blockDim.x + threadIdx.x;
    if (i < SS * NB) g_cnt[i] = 0;
}
__global__ void k_histo(const int* __restrict__ rows) {
    int i = blockIdx.x * blockDim.x + threadIdx.x;
    int s = i >> 16;
    atomicAdd(&g_cnt[s * NB + rows[i]], 1);
}
__global__ void k_scan() {
    int s = blockIdx.x;
    int t = threadIdx.x;
    __shared__ int wsum[32];
    int base = s * NB + t * 4;
    int v0 = g_cnt[base + 0], v1 = g_cnt[base + 1];
    int v2 = g_cnt[base + 2], v3 = g_cnt[base + 3];
    int tot = v0 + v1 + v2 + v3;
    int lane = t & 31, w = t >> 5;
    int x = tot;
#pragma unroll
    for (int d = 1; d < 32; d <<= 1) {
        int y = __shfl_up_sync(0xffffffffu, x, d);
        if (lane >= d) x += y;
    }
    if (lane == 31) wsum[w] = x;
    __syncthreads();
    if (w == 0) {
        int y = wsum[lane];
#pragma unroll
        for (int d = 1; d < 32; d <<= 1) {
            int z = __shfl_up_sync(0xffffffffu, y, d);
            if (lane >= d) y += z;
        }
        wsum[lane] = y;
    }
    __syncthreads();
    int excl = x - tot + (w > 0 ? wsum[w - 1] : 0);
    int ob = s * (NB + 1) + t * 4;
    g_off[ob + 0] = excl;
    g_off[ob + 1] = excl + v0;
    g_off[ob + 2] = excl + v0 + v1;
    g_off[ob + 3] = excl + v0 + v1 + v2;
    g_cur[base + 0] = excl;
    g_cur[base + 1] = excl + v0;
    g_cur[base + 2] = excl + v0 + v1;
    g_cur[base + 3] = excl + v0 + v1 + v2;
    if (t == 1023) g_off[s * (NB + 1) + NB] = excl + tot;
}
__global__ void k_scatter(const int* __restrict__ rows, const int* __restrict__ cols,
                          const float* __restrict__ vals) {
    int i = blockIdx.x * blockDim.x + threadIdx.x;
    int s = i >> 16;
    int r = rows[i];
    int p = atomicAdd(&g_cur[s * NB + r], 1);
    g_edges[s * EE + p] = make_float2(__int_as_float(cols[i]), vals[i]);
}

// ---------------- X0 build: fp32 + fp16 mirror ----------------
__global__ void k_build(const float4* __restrict__ in, const float4* __restrict__ st) {
    int tid = blockIdx.x * blockDim.x + threadIdx.x;
    int q = tid & 31;
    int b = (tid >> 5) & 31;
    int n = tid >> 10;
    float4 v;
    if (q < 16)
        v = in[(size_t)b * (NB * DD / 4) + n * (DD / 4) + q];
    else
        v = st[(size_t)b * (NB * HH / 4) + n * (HH / 4) + (q - 16)];
    size_t off = (size_t)n * ROWLEN + b * FF + q * 4;
    *(float4*)(g_X + off) = v;
    __half2 h0 = __floats2half2_rn(v.x, v.y);
    __half2 h1 = __floats2half2_rn(v.z, v.w);
    uint2 u;
    u.x = *(uint32_t*)&h0;
    u.y = *(uint32_t*)&h1;
    *(uint2*)(g_Xh + off) = u;
}

// ---------------- weight fold + transpose + bf16 split ----------------
// out = X0*(W0-W2-W4) + Y0*W1 + Z0*2W2 + Y1*W3 + Z1*2W4
__global__ void k_wprep(const float* __restrict__ w) {
    int i = blockIdx.x * blockDim.x + threadIdx.x;  // FF*OO
    int f = i & 127;
    int o = i >> 7;
    float w0 = w[(f * MM + 0) * OO + o];
    float w1 = w[(f * MM + 1) * OO + o];
    float w2 = w[(f * MM + 2) * OO + o];
    float w3 = w[(f * MM + 3) * OO + o];
    float w4 = w[(f * MM + 4) * OO + o];
    float p[5] = {w0 - w2 - w4, w1, 2.f * w2, w3, 2.f * w4};
#pragma unroll
    for (int m = 0; m < MM; m++) {
        __nv_bfloat16 hi = __float2bfloat16_rn(p[m]);
        float lo = p[m] - __bfloat162float(hi);
        size_t idx = ((size_t)m * OO + o) * FF + f;
        g_Wth[idx] = hi;
        g_Wtl[idx] = __float2bfloat16_rn(lo);
    }
}

// ---------------- SpMM (fp16 gather, fp32 accum, fp16 out) ----------------
// stage 0: Y_s = A_s X0h   (src slot 0,     dst slot 1+2s)
// stage 1: Z_s = A_s Y_s   (src slot 1+2s,  dst slot 2+2s)
__global__ void __launch_bounds__(256) k_spmm(int stage) {
    int n = blockIdx.x, s = blockIdx.y, t = threadIdx.x;
    int srcm = (stage == 0) ? 0 : 1 + 2 * s;
    int dstm = (stage == 0) ? 1 + 2 * s : 2 + 2 * s;
    const uint4* src = (const uint4*)(g_Xh + (size_t)srcm * NB * ROWLEN);
    uint4* dst = (uint4*)(g_Xh + (size_t)dstm * NB * ROWLEN) + (size_t)n * 512;
    int e   = g_off[s * (NB + 1) + n];
    int end = g_off[s * (NB + 1) + n + 1];
    const float2* ep = g_edges + s * EE;

    float acc[16];
#pragma unroll
    for (int i = 0; i < 16; i++) acc[i] = 0.f;

    for (; e < end; e++) {
        float2 cv = ep[e];
        int c   = __float_as_int(cv.x);
        float v = cv.y;
        const uint4* r = src + (size_t)c * 512;
        uint4 q0 = r[t], q1 = r[t + 256];
        const __half2* h0 = (const __half2*)&q0;
        const __half2* h1 = (const __half2*)&q1;
#pragma unroll
        for (int j = 0; j < 4; j++) {
            float2 f0 = __half22float2(h0[j]);
            float2 f1 = __half22float2(h1[j]);
            acc[2 * j + 0] = fmaf(v, f0.x, acc[2 * j + 0]);
            acc[2 * j + 1] = fmaf(v, f0.y, acc[2 * j + 1]);
            acc[2 * j + 8] = fmaf(v, f1.x, acc[2 * j + 8]);
            acc[2 * j + 9] = fmaf(v, f1.y, acc[2 * j + 9]);
        }
    }

    uint4 o0, o1;
    __half2* p0 = (__half2*)&o0;
    __half2* p1 = (__half2*)&o1;
#pragma unroll
    for (int j = 0; j < 4; j++) {
        p0[j] = __floats2half2_rn(acc[2 * j + 0], acc[2 * j + 1]);
        p1[j] = __floats2half2_rn(acc[2 * j + 8], acc[2 * j + 9]);
    }
    dst[t] = o0;
    dst[t + 256] = o1;
}

// ---------------- mma.sync bf16x3 GEMM ----------------
// D[bn][o] = sum_{m,f} X[m][n][b][f]*Wp[m][f][o] + bias
// m=0 slab from fp32 g_X; m=1..4 from fp16 g_Xh (fp16->bf16 hi/lo split is exact).
#define BK   32
#define BKP  40
#define TSZ  (128 * BKP)
#define STG  (4 * TSZ)
#define GEMM_SMEM (2 * STG * 2)      // 81920 B

__device__ __forceinline__ void mma_bf16(float* c, const uint32_t* a, const uint32_t* b) {
    asm volatile(
        "mma.sync.aligned.m16n8k16.row.col.f32.bf16.bf16.f32 "
        "{%0,%1,%2,%3}, {%4,%5,%6,%7}, {%8,%9}, {%0,%1,%2,%3};\n"
        : "+f"(c[0]), "+f"(c[1]), "+f"(c[2]), "+f"(c[3])
        : "r"(a[0]), "r"(a[1]), "r"(a[2]), "r"(a[3]), "r"(b[0]), "r"(b[1]));
}

__global__ void __launch_bounds__(256) k_gemm_mma(const float* __restrict__ biases,
                                                  float* __restrict__ out) {
    extern __shared__ uint16_t smx[];   // [2][Ah|Al|Bh|Bl][128][BKP]

    const int t = threadIdx.x;
    const int wid = t >> 5, lane = t & 31;
    const int qr = lane >> 2, qc = lane & 3;
    const int wm = wid & 1, wn = wid >> 1;

    const int bn0 = blockIdx.x * 128;
    const int n0 = bn0 & (NB - 1);
    const int b  = bn0 >> 12;

    const int ar = t >> 1, ah = t & 1;   // A: row, 16-elem half
    const int bo = t & 127, bp = t >> 7; // B: o row, 16-bf16 part

    float acc[4][4][4];
#pragma unroll
    for (int i = 0; i < 4; i++)
#pragma unroll
        for (int j = 0; j < 4; j++)
#pragma unroll
            for (int k = 0; k < 4; k++) acc[i][j][k] = 0.f;

    float4 aReg[4];
    uint4  bRegH[2], bRegL[2];

#define LDG_TILE(kt)                                                              \
    {                                                                             \
        const int m_ = (kt) >> 2, f0_ = ((kt) & 3) * BK;                          \
        if (m_ == 0) {                                                            \
            const float4* ap = (const float4*)(g_X +                              \
                ((size_t)(n0 + ar) * BB + b) * FF + f0_ + ah * 16);               \
            aReg[0] = ap[0]; aReg[1] = ap[1]; aReg[2] = ap[2]; aReg[3] = ap[3];   \
        } else {                                                                  \
            const uint4* hp = (const uint4*)(g_Xh +                               \
                (((size_t)m_ * NB + (n0 + ar)) * BB + b) * FF + f0_ + ah * 16);   \
            uint4 h0 = hp[0], h1 = hp[1];                                         \
            const __half2* u0 = (const __half2*)&h0;                              \
            const __half2* u1 = (const __half2*)&h1;                              \
            float2 f;                                                             \
            f = __half22float2(u0[0]); aReg[0].x = f.x; aReg[0].y = f.y;          \
            f = __half22float2(u0[1]); aReg[0].z = f.x; aReg[0].w = f.y;          \
            f = __half22float2(u0[2]); aReg[1].x = f.x; aReg[1].y = f.y;          \
            f = __half22float2(u0[3]); aReg[1].z = f.x; aReg[1].w = f.y;          \
            f = __half22float2(u1[0]); aReg[2].x = f.x; aReg[2].y = f.y;          \
            f = __half22float2(u1[1]); aReg[2].z = f.x; aReg[2].w = f.y;          \
            f = __half22float2(u1[2]); aReg[3].x = f.x; aReg[3].y = f.y;          \
            f = __half22float2(u1[3]); aReg[3].z = f.x; aReg[3].w = f.y;          \
        }                                                                         \
        const uint4* bh = (const uint4*)(g_Wth + ((size_t)m_ * OO + bo) * FF +    \
                                         f0_ + bp * 16);                          \
        const uint4* bl = (const uint4*)(g_Wtl + ((size_t)m_ * OO + bo) * FF +    \
                                         f0_ + bp * 16);                          \
        bRegH[0] = bh[0]; bRegH[1] = bh[1];                                       \
        bRegL[0] = bl[0]; bRegL[1] = bl[1];                                       \
    }

#define STS_TILE(st)                                                              \
    {                                                                             \
        uint16_t* Ah = smx + (st) * STG;                                          \
        uint16_t* Al = Ah + TSZ;                                                  \
        uint16_t* Bh = Ah + 2 * TSZ;                                              \
        uint16_t* Bl = Ah + 3 * TSZ;                                              \
        const float* av = (const float*)aReg;                                     \
        uint32_t* AhR = (uint32_t*)(Ah + ar * BKP + ah * 16);                     \
        uint32_t* AlR = (uint32_t*)(Al + ar * BKP + ah * 16);                     \
        _Pragma("unroll")                                                         \
        for (int j = 0; j < 8; j++) {                                             \
            float x0 = av[2 * j], x1 = av[2 * j + 1];                             \
            __nv_bfloat16 h0 = __float2bfloat16_rn(x0);                           \
            __nv_bfloat16 h1 = __float2bfloat16_rn(x1);                           \
            __nv_bfloat16 l0 = __float2bfloat16_rn(x0 - __bfloat162float(h0));    \
            __nv_bfloat16 l1 = __float2bfloat16_rn(x1 - __bfloat162float(h1));    \
            __nv_bfloat162 hp; hp.x = h0; hp.y = h1;                              \
            __nv_bfloat162 lp; lp.x = l0; lp.y = l1;                              \
            AhR[j] = *(uint32_t*)&hp;                                             \
            AlR[j] = *(uint32_t*)&lp;                                             \
        }                                                                         \
        uint32_t* BhR = (uint32_t*)(Bh + bo * BKP + bp * 16);                     \
        uint32_t* BlR = (uint32_t*)(Bl + bo * BKP + bp * 16);                     \
        const uint32_t* bhv = (const uint32_t*)bRegH;                             \
        const uint32_t* blv = (const uint32_t*)bRegL;                             \
        _Pragma("unroll")                                                         \
        for (int j = 0; j < 8; j++) { BhR[j] = bhv[j]; BlR[j] = blv[j]; }         \
    }

    LDG_TILE(0);
    STS_TILE(0);
    __syncthreads();

    for (int kt = 0; kt < 20; kt++) {
        const int st = kt & 1;
        if (kt < 19) LDG_TILE(kt + 1);

        const uint16_t* Ah = smx + st * STG;
        const uint16_t* Al = Ah + TSZ;
        const uint16_t* Bh = Ah + 2 * TSZ;
        const uint16_t* Bl = Ah + 3 * TSZ;

#pragma unroll
        for (int kk = 0; kk < BK; kk += 16) {
            uint32_t fbh[4][2], fbl[4][2];
#pragma unroll
            for (int ni = 0; ni < 4; ni++) {
                int nb = wn * 32 + ni * 8 + qr;
                int w0 = nb * BKP + kk + 2 * qc;
                fbh[ni][0] = *(const uint32_t*)&Bh[w0];
                fbh[ni][1] = *(const uint32_t*)&Bh[w0 + 8];
                fbl[ni][0] = *(const uint32_t*)&Bl[w0];
                fbl[ni][1] = *(const uint32_t*)&Bl[w0 + 8];
            }
#pragma unroll
            for (int mi = 0; mi < 4; mi++) {
                int rb = wm * 64 + mi * 16 + qr;
                int w0 = rb * BKP + kk + 2 * qc;
                uint32_t fah[4], fal[4];
                fah[0] = *(const uint32_t*)&Ah[w0];
                fah[1] = *(const uint32_t*)&Ah[w0 + 8 * BKP];
                fah[2] = *(const uint32_t*)&Ah[w0 + 8];
                fah[3] = *(const uint32_t*)&Ah[w0 + 8 * BKP + 8];
                fal[0] = *(const uint32_t*)&Al[w0];
                fal[1] = *(const uint32_t*)&Al[w0 + 8 * BKP];
                fal[2] = *(const uint32_t*)&Al[w0 + 8];
                fal[3] = *(const uint32_t*)&Al[w0 + 8 * BKP + 8];
#pragma unroll
                for (int ni = 0; ni < 4; ni++) {
                    mma_bf16(acc[mi][ni], fah, fbh[ni]);
                    mma_bf16(acc[mi][ni], fah, fbl[ni]);
                    mma_bf16(acc[mi][ni], fal, fbh[ni]);
                }
            }
        }

        if (kt < 19) {
            STS_TILE(1 - st);
        }
        __syncthreads();
    }

#pragma unroll
    for (int mi = 0; mi < 4; mi++) {
#pragma unroll
        for (int ni = 0; ni < 4; ni++) {
            int col = wn * 32 + ni * 8 + 2 * qc;
            float b0 = biases[col], b1 = biases[col + 1];
            int r0 = bn0 + wm * 64 + mi * 16 + qr;
            float2 v0 = make_float2(acc[mi][ni][0] + b0, acc[mi][ni][1] + b1);
            float2 v1 = make_float2(acc[mi][ni][2] + b0, acc[mi][ni][3] + b1);
            *(float2*)(out + (size_t)r0 * OO + col)       = v0;
            *(float2*)(out + (size_t)(r0 + 8) * OO + col) = v1;
        }
    }
#undef LDG_TILE
#undef STS_TILE
}

// ---------------- launch ----------------
extern "C" void kernel_launch(void* const* d_in, const int* in_sizes, int n_in,
                              void* d_out, int out_size) {
    const float* inputs = (const float*)d_in[0];
    const float* state  = (const float*)d_in[1];
    const int*   rows   = (const int*)d_in[2];
    const int*   cols   = (const int*)d_in[3];
    const float* vals   = (const float*)d_in[4];
    const float* weight = (const float*)d_in[5];
    const float* biases = (const float*)d_in[6];
    float* out = (float*)d_out;
    (void)in_sizes; (void)n_in; (void)out_size;

    cudaFuncSetAttribute(k_gemm_mma, cudaFuncAttributeMaxDynamicSharedMemorySize,
                         GEMM_SMEM);

    k_zero_cnt<<<(SS * NB + 255) / 256, 256>>>();
    k_histo<<<(SS * EE) / 256, 256>>>(rows);
    k_scan<<<SS, 1024>>>();
    k_scatter<<<(SS * EE) / 256, 256>>>(rows, cols, vals);
    k_build<<<(NB * BB * 32) / 256, 256>>>((const float4*)inputs,
                                           (const float4*)state);
    k_wprep<<<(FF * OO) / 256, 256>>>(weight);
    k_spmm<<<dim3(NB, SS), 256>>>(0);
    k_spmm<<<dim3(NB, SS), 256>>>(1);
    k_gemm_mma<<<(BB * NB) / 128, 256, GEMM_SMEM>>>(biases, out);
}

// round 5
// speedup vs baseline: 1.7068x; 1.1144x over previous
#include <cuda_runtime.h>
#include <cuda_bf16.h>
#include <cuda_fp16.h>
#include <cstdint>

// DiffusionGraphConv — GB300 sm_103 (baseline PTX; no tcgen05 in this toolchain)
//   1) CSR build per support                                    ~10us
//   2) X0 build: fp32 [n][b][f] + fp16 mirror                   ~25us
//   3) Wp fold + transpose + bf16 hi/lo split                   ~3us
//   4) SpMM x4 fp16 gather, 4-edge unroll (MLP=8)               ~220us
//   5) GEMM bf16x3 mma.sync + ldmatrix fragments                ~95us

#define NB 4096
#define BB 32
#define DD 64
#define HH 64
#define FF 128
#define EE 65536
#define SS 2
#define MM 5
#define OO 128
#define ROWLEN (BB * FF)        // 4096 elements per node-row
#define ROWLEN4 (ROWLEN / 4)

// ---- device scratch ----
__device__ float  g_X[(size_t)NB * ROWLEN];            // X0 fp32, 64MB (GEMM m=0)
__device__ __half g_Xh[(size_t)MM * NB * ROWLEN];      // [X0h,Y0,Z0,Y1,Z1] fp16, 160MB
__device__ float2 g_edges[SS * EE];
__device__ int    g_off[SS * (NB + 1)];
__device__ int    g_cur[SS * NB];
__device__ int    g_cnt[SS * NB];
__device__ __nv_bfloat16 g_Wth[MM * OO * FF];          // folded, transposed [m][o][f], hi
__device__ __nv_bfloat16 g_Wtl[MM * OO * FF];          // lo

// ---------------- CSR build ----------------
__global__ void k_zero_cnt() {
    int i = blockIdx.x * blockDim.x + threadIdx.x;
    if (i < SS * NB) g_cnt[i] = 0;
}
__global__ void k_histo(const int* __restrict__ rows) {
    int i = blockIdx.x * blockDim.x + threadIdx.x;
    int s = i >> 16;
    atomicAdd(&g_cnt[s * NB + rows[i]], 1);
}
__global__ void k_scan() {
    int s = blockIdx.x;
    int t = threadIdx.x;
    __shared__ int wsum[32];
    int base = s * NB + t * 4;
    int v0 = g_cnt[base + 0], v1 = g_cnt[base + 1];
    int v2 = g_cnt[base + 2], v3 = g_cnt[base + 3];
    int tot = v0 + v1 + v2 + v3;
    int lane = t & 31, w = t >> 5;
    int x = tot;
#pragma unroll
    for (int d = 1; d < 32; d <<= 1) {
        int y = __shfl_up_sync(0xffffffffu, x, d);
        if (lane >= d) x += y;
    }
    if (lane == 31) wsum[w] = x;
    __syncthreads();
    if (w == 0) {
        int y = wsum[lane];
#pragma unroll
        for (int d = 1; d < 32; d <<= 1) {
            int z = __shfl_up_sync(0xffffffffu, y, d);
            if (lane >= d) y += z;
        }
        wsum[lane] = y;
    }
    __syncthreads();
    int excl = x - tot + (w > 0 ? wsum[w - 1] : 0);
    int ob = s * (NB + 1) + t * 4;
    g_off[ob + 0] = excl;
    g_off[ob + 1] = excl + v0;
    g_off[ob + 2] = excl + v0 + v1;
    g_off[ob + 3] = excl + v0 + v1 + v2;
    g_cur[base + 0] = excl;
    g_cur[base + 1] = excl + v0;
    g_cur[base + 2] = excl + v0 + v1;
    g_cur[base + 3] = excl + v0 + v1 + v2;
    if (t == 1023) g_off[s * (NB + 1) + NB] = excl + tot;
}
__global__ void k_scatter(const int* __restrict__ rows, const int* __restrict__ cols,
                          const float* __restrict__ vals) {
    int i = blockIdx.x * blockDim.x + threadIdx.x;
    int s = i >> 16;
    int r = rows[i];
    int p = atomicAdd(&g_cur[s * NB + r], 1);
    g_edges[s * EE + p] = make_float2(__int_as_float(cols[i]), vals[i]);
}

// ---------------- X0 build: fp32 + fp16 mirror ----------------
__global__ void k_build(const float4* __restrict__ in, const float4* __restrict__ st) {
    int tid = blockIdx.x * blockDim.x + threadIdx.x;
    int q = tid & 31;
    int b = (tid >> 5) & 31;
    int n = tid >> 10;
    float4 v;
    if (q < 16)
        v = in[(size_t)b * (NB * DD / 4) + n * (DD / 4) + q];
    else
        v = st[(size_t)b * (NB * HH / 4) + n * (HH / 4) + (q - 16)];
    size_t off = (size_t)n * ROWLEN + b * FF + q * 4;
    *(float4*)(g_X + off) = v;
    __half2 h0 = __floats2half2_rn(v.x, v.y);
    __half2 h1 = __floats2half2_rn(v.z, v.w);
    uint2 u;
    u.x = *(uint32_t*)&h0;
    u.y = *(uint32_t*)&h1;
    *(uint2*)(g_Xh + off) = u;
}

// ---------------- weight fold + transpose + bf16 split ----------------
// out = X0*(W0-W2-W4) + Y0*W1 + Z0*2W2 + Y1*W3 + Z1*2W4
__global__ void k_wprep(const float* __restrict__ w) {
    int i = blockIdx.x * blockDim.x + threadIdx.x;  // FF*OO
    int f = i & 127;
    int o = i >> 7;
    float w0 = w[(f * MM + 0) * OO + o];
    float w1 = w[(f * MM + 1) * OO + o];
    float w2 = w[(f * MM + 2) * OO + o];
    float w3 = w[(f * MM + 3) * OO + o];
    float w4 = w[(f * MM + 4) * OO + o];
    float p[5] = {w0 - w2 - w4, w1, 2.f * w2, w3, 2.f * w4};
#pragma unroll
    for (int m = 0; m < MM; m++) {
        __nv_bfloat16 hi = __float2bfloat16_rn(p[m]);
        float lo = p[m] - __bfloat162float(hi);
        size_t idx = ((size_t)m * OO + o) * FF + f;
        g_Wth[idx] = hi;
        g_Wtl[idx] = __float2bfloat16_rn(lo);
    }
}

// ---------------- SpMM (fp16 gather, fp32 accum, fp16 out, 4-edge unroll) ----------------
__device__ __forceinline__ void spmm_acc(float* acc, uint4 q0, uint4 q1, float v) {
    const __half2* h0 = (const __half2*)&q0;
    const __half2* h1 = (const __half2*)&q1;
#pragma unroll
    for (int j = 0; j < 4; j++) {
        float2 f0 = __half22float2(h0[j]);
        float2 f1 = __half22float2(h1[j]);
        acc[2 * j + 0] = fmaf(v, f0.x, acc[2 * j + 0]);
        acc[2 * j + 1] = fmaf(v, f0.y, acc[2 * j + 1]);
        acc[2 * j + 8] = fmaf(v, f1.x, acc[2 * j + 8]);
        acc[2 * j + 9] = fmaf(v, f1.y, acc[2 * j + 9]);
    }
}

__global__ void __launch_bounds__(256) k_spmm(int stage) {
    int n = blockIdx.x, s = blockIdx.y, t = threadIdx.x;
    int srcm = (stage == 0) ? 0 : 1 + 2 * s;
    int dstm = (stage == 0) ? 1 + 2 * s : 2 + 2 * s;
    const uint4* src = (const uint4*)(g_Xh + (size_t)srcm * NB * ROWLEN);
    uint4* dst = (uint4*)(g_Xh + (size_t)dstm * NB * ROWLEN) + (size_t)n * 512;
    int e   = g_off[s * (NB + 1) + n];
    int end = g_off[s * (NB + 1) + n + 1];
    const float2* ep = g_edges + s * EE;

    float acc[16];
#pragma unroll
    for (int i = 0; i < 16; i++) acc[i] = 0.f;

    for (; e + 4 <= end; e += 4) {
        float2 cv0 = ep[e + 0], cv1 = ep[e + 1];
        float2 cv2 = ep[e + 2], cv3 = ep[e + 3];
        const uint4* r0 = src + (size_t)__float_as_int(cv0.x) * 512;
        const uint4* r1 = src + (size_t)__float_as_int(cv1.x) * 512;
        const uint4* r2 = src + (size_t)__float_as_int(cv2.x) * 512;
        const uint4* r3 = src + (size_t)__float_as_int(cv3.x) * 512;
        uint4 a0 = r0[t], b0 = r0[t + 256];
        uint4 a1 = r1[t], b1 = r1[t + 256];
        uint4 a2 = r2[t], b2 = r2[t + 256];
        uint4 a3 = r3[t], b3 = r3[t + 256];
        spmm_acc(acc, a0, b0, cv0.y);
        spmm_acc(acc, a1, b1, cv1.y);
        spmm_acc(acc, a2, b2, cv2.y);
        spmm_acc(acc, a3, b3, cv3.y);
    }
    for (; e < end; e++) {
        float2 cv = ep[e];
        const uint4* r = src + (size_t)__float_as_int(cv.x) * 512;
        uint4 a = r[t], b = r[t + 256];
        spmm_acc(acc, a, b, cv.y);
    }

    uint4 o0, o1;
    __half2* p0 = (__half2*)&o0;
    __half2* p1 = (__half2*)&o1;
#pragma unroll
    for (int j = 0; j < 4; j++) {
        p0[j] = __floats2half2_rn(acc[2 * j + 0], acc[2 * j + 1]);
        p1[j] = __floats2half2_rn(acc[2 * j + 8], acc[2 * j + 9]);
    }
    dst[t] = o0;
    dst[t + 256] = o1;
}

// ---------------- mma.sync bf16x3 GEMM with ldmatrix fragments ----------------
#define BK   32
#define BKP  40
#define TSZ  (128 * BKP)
#define STG  (4 * TSZ)
#define GEMM_SMEM (2 * STG * 2)      // 81920 B

__device__ __forceinline__ void mma_bf16(float* c, const uint32_t* a, const uint32_t* b) {
    asm volatile(
        "mma.sync.aligned.m16n8k16.row.col.f32.bf16.bf16.f32 "
        "{%0,%1,%2,%3}, {%4,%5,%6,%7}, {%8,%9}, {%0,%1,%2,%3};\n"
        : "+f"(c[0]), "+f"(c[1]), "+f"(c[2]), "+f"(c[3])
        : "r"(a[0]), "r"(a[1]), "r"(a[2]), "r"(a[3]), "r"(b[0]), "r"(b[1]));
}
__device__ __forceinline__ void ldsm_x4(uint32_t* r, uint32_t saddr) {
    asm volatile("ldmatrix.sync.aligned.m8n8.x4.shared.b16 {%0,%1,%2,%3}, [%4];"
                 : "=r"(r[0]), "=r"(r[1]), "=r"(r[2]), "=r"(r[3]) : "r"(saddr));
}

__global__ void __launch_bounds__(256) k_gemm_mma(const float* __restrict__ biases,
                                                  float* __restrict__ out) {
    extern __shared__ uint16_t smx[];   // [2][Ah|Al|Bh|Bl][128][BKP]
    const uint32_t smem0 = (uint32_t)__cvta_generic_to_shared(smx);

    const int t = threadIdx.x;
    const int wid = t >> 5, lane = t & 31;
    const int qr = lane >> 2, qc = lane & 3;
    const int wm = wid & 1, wn = wid >> 1;

    const int bn0 = blockIdx.x * 128;
    const int n0 = bn0 & (NB - 1);
    const int b  = bn0 >> 12;

    const int ar = t >> 1, ah = t & 1;   // A ldg: row, 16-elem half
    const int bo = t & 127, bp = t >> 7; // B ldg: o row, 16-bf16 part

    // ldmatrix per-lane offsets (u16 units within a tile)
    //  A tile (rows x k):  mats 0..3 = (r,k),(r+8,k),(r,k+8),(r+8,k+8)
    const int aRowOff = (wm * 64 + (lane & 15)) * BKP + ((lane >> 4) << 3);
    //  B tile ([n][k]):    mats 0..3 = b0/b1 of n-tile p.0, then p.1
    const int bRowOff = (wn * 32 + ((lane >> 4) << 3) + (lane & 7)) * BKP + (lane & 8);

    float acc[4][4][4];
#pragma unroll
    for (int i = 0; i < 4; i++)
#pragma unroll
        for (int j = 0; j < 4; j++)
#pragma unroll
            for (int k = 0; k < 4; k++) acc[i][j][k] = 0.f;

    float4 aReg[4];
    uint4  bRegH[2], bRegL[2];

#define LDG_TILE(kt)                                                              \
    {                                                                             \
        const int m_ = (kt) >> 2, f0_ = ((kt) & 3) * BK;                          \
        if (m_ == 0) {                                                            \
            const float4* ap = (const float4*)(g_X +                              \
                ((size_t)(n0 + ar) * BB + b) * FF + f0_ + ah * 16);               \
            aReg[0] = ap[0]; aReg[1] = ap[1]; aReg[2] = ap[2]; aReg[3] = ap[3];   \
        } else {                                                                  \
            const uint4* hp = (const uint4*)(g_Xh +                               \
                (((size_t)m_ * NB + (n0 + ar)) * BB + b) * FF + f0_ + ah * 16);   \
            uint4 h0 = hp[0], h1 = hp[1];                                         \
            const __half2* u0 = (const __half2*)&h0;                              \
            const __half2* u1 = (const __half2*)&h1;                              \
            float2 f;                                                             \
            f = __half22float2(u0[0]); aReg[0].x = f.x; aReg[0].y = f.y;          \
            f = __half22float2(u0[1]); aReg[0].z = f.x; aReg[0].w = f.y;          \
            f = __half22float2(u0[2]); aReg[1].x = f.x; aReg[1].y = f.y;          \
            f = __half22float2(u0[3]); aReg[1].z = f.x; aReg[1].w = f.y;          \
            f = __half22float2(u1[0]); aReg[2].x = f.x; aReg[2].y = f.y;          \
            f = __half22float2(u1[1]); aReg[2].z = f.x; aReg[2].w = f.y;          \
            f = __half22float2(u1[2]); aReg[3].x = f.x; aReg[3].y = f.y;          \
            f = __half22float2(u1[3]); aReg[3].z = f.x; aReg[3].w = f.y;          \
        }                                                                         \
        const uint4* bh = (const uint4*)(g_Wth + ((size_t)m_ * OO + bo) * FF +    \
                                         f0_ + bp * 16);                          \
        const uint4* bl = (const uint4*)(g_Wtl + ((size_t)m_ * OO + bo) * FF +    \
                                         f0_ + bp * 16);                          \
        bRegH[0] = bh[0]; bRegH[1] = bh[1];                                       \
        bRegL[0] = bl[0]; bRegL[1] = bl[1];                                       \
    }

#define STS_TILE(st)                                                              \
    {                                                                             \
        uint16_t* Ah = smx + (st) * STG;                                          \
        uint16_t* Al = Ah + TSZ;                                                  \
        uint16_t* Bh = Ah + 2 * TSZ;                                              \
        uint16_t* Bl = Ah + 3 * TSZ;                                              \
        const float* av = (const float*)aReg;                                     \
        uint32_t* AhR = (uint32_t*)(Ah + ar * BKP + ah * 16);                     \
        uint32_t* AlR = (uint32_t*)(Al + ar * BKP + ah * 16);                     \
        _Pragma("unroll")                                                         \
        for (int j = 0; j < 8; j++) {                                             \
            float x0 = av[2 * j], x1 = av[2 * j + 1];                             \
            __nv_bfloat16 h0 = __float2bfloat16_rn(x0);                           \
            __nv_bfloat16 h1 = __float2bfloat16_rn(x1);                           \
            __nv_bfloat16 l0 = __float2bfloat16_rn(x0 - __bfloat162float(h0));    \
            __nv_bfloat16 l1 = __float2bfloat16_rn(x1 - __bfloat162float(h1));    \
            __nv_bfloat162 hp; hp.x = h0; hp.y = h1;                              \
            __nv_bfloat162 lp; lp.x = l0; lp.y = l1;                              \
            AhR[j] = *(uint32_t*)&hp;                                             \
            AlR[j] = *(uint32_t*)&lp;                                             \
        }                                                                         \
        uint32_t* BhR = (uint32_t*)(Bh + bo * BKP + bp * 16);                     \
        uint32_t* BlR = (uint32_t*)(Bl + bo * BKP + bp * 16);                     \
        const uint32_t* bhv = (const uint32_t*)bRegH;                             \
        const uint32_t* blv = (const uint32_t*)bRegL;                             \
        _Pragma("unroll")                                                         \
        for (int j = 0; j < 8; j++) { BhR[j] = bhv[j]; BlR[j] = blv[j]; }         \
    }

    LDG_TILE(0);
    STS_TILE(0);
    __syncthreads();

    for (int kt = 0; kt < 20; kt++) {
        const int st = kt & 1;
        if (kt < 19) LDG_TILE(kt + 1);

        const uint32_t baseAh = smem0 + (st * STG) * 2;
        const uint32_t baseAl = baseAh + TSZ * 2;
        const uint32_t baseBh = baseAh + 2 * TSZ * 2;
        const uint32_t baseBl = baseAh + 3 * TSZ * 2;

#pragma unroll
        for (int kk = 0; kk < BK; kk += 16) {
            // B fragments: 2 n-tile-pairs x {hi,lo}, each ldsm.x4 = {b0,b1}x2 tiles
            uint32_t fbh[4][2], fbl[4][2];
#pragma unroll
            for (int p = 0; p < 2; p++) {
                uint32_t r[4];
                uint32_t off = (bRowOff + p * 16 * BKP + kk) * 2;
                ldsm_x4(r, baseBh + off);
                fbh[2 * p][0] = r[0]; fbh[2 * p][1] = r[1];
                fbh[2 * p + 1][0] = r[2]; fbh[2 * p + 1][1] = r[3];
                ldsm_x4(r, baseBl + off);
                fbl[2 * p][0] = r[0]; fbl[2 * p][1] = r[1];
                fbl[2 * p + 1][0] = r[2]; fbl[2 * p + 1][1] = r[3];
            }
#pragma unroll
            for (int mi = 0; mi < 4; mi++) {
                uint32_t fah[4], fal[4];
                uint32_t off = (aRowOff + mi * 16 * BKP + kk) * 2;
                ldsm_x4(fah, baseAh + off);
                ldsm_x4(fal, baseAl + off);
#pragma unroll
                for (int ni = 0; ni < 4; ni++) {
                    mma_bf16(acc[mi][ni], fah, fbh[ni]);
                    mma_bf16(acc[mi][ni], fah, fbl[ni]);
                    mma_bf16(acc[mi][ni], fal, fbh[ni]);
                }
            }
        }

        if (kt < 19) {
            STS_TILE(1 - st);
        }
        __syncthreads();
    }

#pragma unroll
    for (int mi = 0; mi < 4; mi++) {
#pragma unroll
        for (int ni = 0; ni < 4; ni++) {
            int col = wn * 32 + ni * 8 + 2 * qc;
            float b0 = biases[col], b1 = biases[col + 1];
            int r0 = bn0 + wm * 64 + mi * 16 + qr;
            float2 v0 = make_float2(acc[mi][ni][0] + b0, acc[mi][ni][1] + b1);
            float2 v1 = make_float2(acc[mi][ni][2] + b0, acc[mi][ni][3] + b1);
            *(float2*)(out + (size_t)r0 * OO + col)       = v0;
            *(float2*)(out + (size_t)(r0 + 8) * OO + col) = v1;
        }
    }
#undef LDG_TILE
#undef STS_TILE
}

// ---------------- launch ----------------
extern "C" void kernel_launch(void* const* d_in, const int* in_sizes, int n_in,
                              void* d_out, int out_size) {
    const float* inputs = (const float*)d_in[0];
    const float* state  = (const float*)d_in[1];
    const int*   rows   = (const int*)d_in[2];
    const int*   cols   = (const int*)d_in[3];
    const float* vals   = (const float*)d_in[4];
    const float* weight = (const float*)d_in[5];
    const float* biases = (const float*)d_in[6];
    float* out = (float*)d_out;
    (void)in_sizes; (void)n_in; (void)out_size;

    cudaFuncSetAttribute(k_gemm_mma, cudaFuncAttributeMaxDynamicSharedMemorySize,
                         GEMM_SMEM);

    k_zero_cnt<<<(SS * NB + 255) / 256, 256>>>();
    k_histo<<<(SS * EE) / 256, 256>>>(rows);
    k_scan<<<SS, 1024>>>();
    k_scatter<<<(SS * EE) / 256, 256>>>(rows, cols, vals);
    k_build<<<(NB * BB * 32) / 256, 256>>>((const float4*)inputs,
                                           (const float4*)state);
    k_wprep<<<(FF * OO) / 256, 256>>>(weight);
    k_spmm<<<dim3(NB, SS), 256>>>(0);
    k_spmm<<<dim3(NB, SS), 256>>>(1);
    k_gemm_mma<<<(BB * NB) / 128, 256, GEMM_SMEM>>>(biases, out);
}

// round 6
// speedup vs baseline: 1.7148x; 1.0047x over previous
#include <cuda_runtime.h>
#include <cuda_bf16.h>
#include <cuda_fp16.h>
#include <cstdint>

// DiffusionGraphConv — GB300 sm_103 (baseline PTX; no tcgen05 in this toolchain)
//   1) CSR build per support                                    ~10us
//   2) X0 build: fp32 [n][b][f] + fp16 mirror                   ~25us
//   3) Wp fold + transpose + bf16 hi/lo split                   ~3us
//   4) SpMM x4 fp16 gather, half-row CTAs, 8-edge unroll        ~200us
//   5) GEMM bf16x3 mma.sync + ldmatrix fragments                ~115us

#define NB 4096
#define BB 32
#define DD 64
#define HH 64
#define FF 128
#define EE 65536
#define SS 2
#define MM 5
#define OO 128
#define ROWLEN (BB * FF)        // 4096 elements per node-row
#define ROWLEN4 (ROWLEN / 4)

// ---- device scratch ----
__device__ float  g_X[(size_t)NB * ROWLEN];            // X0 fp32, 64MB (GEMM m=0)
__device__ __half g_Xh[(size_t)MM * NB * ROWLEN];      // [X0h,Y0,Z0,Y1,Z1] fp16, 160MB
__device__ float2 g_edges[SS * EE];
__device__ int    g_off[SS * (NB + 1)];
__device__ int    g_cur[SS * NB];
__device__ int    g_cnt[SS * NB];
__device__ __nv_bfloat16 g_Wth[MM * OO * FF];          // folded, transposed [m][o][f], hi
__device__ __nv_bfloat16 g_Wtl[MM * OO * FF];          // lo

// ---------------- CSR build ----------------
__global__ void k_zero_cnt() {
    int i = blockIdx.x * blockDim.x + threadIdx.x;
    if (i < SS * NB) g_cnt[i] = 0;
}
__global__ void k_histo(const int* __restrict__ rows) {
    int i = blockIdx.x * blockDim.x + threadIdx.x;
    int s = i >> 16;
    atomicAdd(&g_cnt[s * NB + rows[i]], 1);
}
__global__ void k_scan() {
    int s = blockIdx.x;
    int t = threadIdx.x;
    __shared__ int wsum[32];
    int base = s * NB + t * 4;
    int v0 = g_cnt[base + 0], v1 = g_cnt[base + 1];
    int v2 = g_cnt[base + 2], v3 = g_cnt[base + 3];
    int tot = v0 + v1 + v2 + v3;
    int lane = t & 31, w = t >> 5;
    int x = tot;
#pragma unroll
    for (int d = 1; d < 32; d <<= 1) {
        int y = __shfl_up_sync(0xffffffffu, x, d);
        if (lane >= d) x += y;
    }
    if (lane == 31) wsum[w] = x;
    __syncthreads();
    if (w == 0) {
        int y = wsum[lane];
#pragma unroll
        for (int d = 1; d < 32; d <<= 1) {
            int z = __shfl_up_sync(0xffffffffu, y, d);
            if (lane >= d) y += z;
        }
        wsum[lane] = y;
    }
    __syncthreads();
    int excl = x - tot + (w > 0 ? wsum[w - 1] : 0);
    int ob = s * (NB + 1) + t * 4;
    g_off[ob + 0] = excl;
    g_off[ob + 1] = excl + v0;
    g_off[ob + 2] = excl + v0 + v1;
    g_off[ob + 3] = excl + v0 + v1 + v2;
    g_cur[base + 0] = excl;
    g_cur[base + 1] = excl + v0;
    g_cur[base + 2] = excl + v0 + v1;
    g_cur[base + 3] = excl + v0 + v1 + v2;
    if (t == 1023) g_off[s * (NB + 1) + NB] = excl + tot;
}
__global__ void k_scatter(const int* __restrict__ rows, const int* __restrict__ cols,
                          const float* __restrict__ vals) {
    int i = blockIdx.x * blockDim.x + threadIdx.x;
    int s = i >> 16;
    int r = rows[i];
    int p = atomicAdd(&g_cur[s * NB + r], 1);
    g_edges[s * EE + p] = make_float2(__int_as_float(cols[i]), vals[i]);
}

// ---------------- X0 build: fp32 + fp16 mirror ----------------
__global__ void k_build(const float4* __restrict__ in, const float4* __restrict__ st) {
    int tid = blockIdx.x * blockDim.x + threadIdx.x;
    int q = tid & 31;
    int b = (tid >> 5) & 31;
    int n = tid >> 10;
    float4 v;
    if (q < 16)
        v = in[(size_t)b * (NB * DD / 4) + n * (DD / 4) + q];
    else
        v = st[(size_t)b * (NB * HH / 4) + n * (HH / 4) + (q - 16)];
    size_t off = (size_t)n * ROWLEN + b * FF + q * 4;
    *(float4*)(g_X + off) = v;
    __half2 h0 = __floats2half2_rn(v.x, v.y);
    __half2 h1 = __floats2half2_rn(v.z, v.w);
    uint2 u;
    u.x = *(uint32_t*)&h0;
    u.y = *(uint32_t*)&h1;
    *(uint2*)(g_Xh + off) = u;
}

// ---------------- weight fold + transpose + bf16 split ----------------
// out = X0*(W0-W2-W4) + Y0*W1 + Z0*2W2 + Y1*W3 + Z1*2W4
__global__ void k_wprep(const float* __restrict__ w) {
    int i = blockIdx.x * blockDim.x + threadIdx.x;  // FF*OO
    int f = i & 127;
    int o = i >> 7;
    float w0 = w[(f * MM + 0) * OO + o];
    float w1 = w[(f * MM + 1) * OO + o];
    float w2 = w[(f * MM + 2) * OO + o];
    float w3 = w[(f * MM + 3) * OO + o];
    float w4 = w[(f * MM + 4) * OO + o];
    float p[5] = {w0 - w2 - w4, w1, 2.f * w2, w3, 2.f * w4};
#pragma unroll
    for (int m = 0; m < MM; m++) {
        __nv_bfloat16 hi = __float2bfloat16_rn(p[m]);
        float lo = p[m] - __bfloat162float(hi);
        size_t idx = ((size_t)m * OO + o) * FF + f;
        g_Wth[idx] = hi;
        g_Wtl[idx] = __float2bfloat16_rn(lo);
    }
}

// ---------------- SpMM: fp16 gather, half-row CTAs, 8-edge unroll ----------------
__device__ __forceinline__ void spmm_acc8(float* acc, uint4 q, float v) {
    const __half2* h = (const __half2*)&q;
#pragma unroll
    for (int j = 0; j < 4; j++) {
        float2 f = __half22float2(h[j]);
        acc[2 * j + 0] = fmaf(v, f.x, acc[2 * j + 0]);
        acc[2 * j + 1] = fmaf(v, f.y, acc[2 * j + 1]);
    }
}

__global__ void __launch_bounds__(256) k_spmm(int stage) {
    const int n = blockIdx.x, s = blockIdx.y;
    const int col = blockIdx.z * 256 + threadIdx.x;   // uint4 index in row [0,512)
    const int srcm = (stage == 0) ? 0 : 1 + 2 * s;
    const int dstm = (stage == 0) ? 1 + 2 * s : 2 + 2 * s;
    const uint4* src = (const uint4*)(g_Xh + (size_t)srcm * NB * ROWLEN) + col;
    uint4* dst = (uint4*)(g_Xh + (size_t)dstm * NB * ROWLEN) + (size_t)n * 512 + col;
    int e   = g_off[s * (NB + 1) + n];
    int end = g_off[s * (NB + 1) + n + 1];
    const float2* ep = g_edges + s * EE;

    float acc[8];
#pragma unroll
    for (int i = 0; i < 8; i++) acc[i] = 0.f;

    for (; e + 8 <= end; e += 8) {
        float2 cv[8];
        uint4 r[8];
#pragma unroll
        for (int i = 0; i < 8; i++) cv[i] = ep[e + i];
#pragma unroll
        for (int i = 0; i < 8; i++)
            r[i] = src[(size_t)__float_as_int(cv[i].x) * 512];
#pragma unroll
        for (int i = 0; i < 8; i++) spmm_acc8(acc, r[i], cv[i].y);
    }
    for (; e < end; e++) {
        float2 cv = ep[e];
        uint4 r = src[(size_t)__float_as_int(cv.x) * 512];
        spmm_acc8(acc, r, cv.y);
    }

    uint4 o;
    __half2* po = (__half2*)&o;
#pragma unroll
    for (int j = 0; j < 4; j++)
        po[j] = __floats2half2_rn(acc[2 * j + 0], acc[2 * j + 1]);
    *dst = o;
}

// ---------------- mma.sync bf16x3 GEMM with ldmatrix fragments ----------------
#define BK   32
#define BKP  40
#define TSZ  (128 * BKP)
#define STG  (4 * TSZ)
#define GEMM_SMEM (2 * STG * 2)      // 81920 B

__device__ __forceinline__ void mma_bf16(float* c, const uint32_t* a, const uint32_t* b) {
    asm volatile(
        "mma.sync.aligned.m16n8k16.row.col.f32.bf16.bf16.f32 "
        "{%0,%1,%2,%3}, {%4,%5,%6,%7}, {%8,%9}, {%0,%1,%2,%3};\n"
        : "+f"(c[0]), "+f"(c[1]), "+f"(c[2]), "+f"(c[3])
        : "r"(a[0]), "r"(a[1]), "r"(a[2]), "r"(a[3]), "r"(b[0]), "r"(b[1]));
}
__device__ __forceinline__ void ldsm_x4(uint32_t* r, uint32_t saddr) {
    asm volatile("ldmatrix.sync.aligned.m8n8.x4.shared.b16 {%0,%1,%2,%3}, [%4];"
                 : "=r"(r[0]), "=r"(r[1]), "=r"(r[2]), "=r"(r[3]) : "r"(saddr));
}

__global__ void __launch_bounds__(256) k_gemm_mma(const float* __restrict__ biases,
                                                  float* __restrict__ out) {
    extern __shared__ uint16_t smx[];   // [2][Ah|Al|Bh|Bl][128][BKP]
    const uint32_t smem0 = (uint32_t)__cvta_generic_to_shared(smx);

    const int t = threadIdx.x;
    const int wid = t >> 5, lane = t & 31;
    const int qr = lane >> 2, qc = lane & 3;
    const int wm = wid & 1, wn = wid >> 1;

    const int bn0 = blockIdx.x * 128;
    const int n0 = bn0 & (NB - 1);
    const int b  = bn0 >> 12;

    const int ar = t >> 1, ah = t & 1;   // A ldg: row, 16-elem half
    const int bo = t & 127, bp = t >> 7; // B ldg: o row, 16-bf16 part

    const int aRowOff = (wm * 64 + (lane & 15)) * BKP + ((lane >> 4) << 3);
    const int bRowOff = (wn * 32 + ((lane >> 4) << 3) + (lane & 7)) * BKP + (lane & 8);

    float acc[4][4][4];
#pragma unroll
    for (int i = 0; i < 4; i++)
#pragma unroll
        for (int j = 0; j < 4; j++)
#pragma unroll
            for (int k = 0; k < 4; k++) acc[i][j][k] = 0.f;

    float4 aReg[4];
    uint4  bRegH[2], bRegL[2];

#define LDG_TILE(kt)                                                              \
    {                                                                             \
        const int m_ = (kt) >> 2, f0_ = ((kt) & 3) * BK;                          \
        if (m_ == 0) {                                                            \
            const float4* ap = (const float4*)(g_X +                              \
                ((size_t)(n0 + ar) * BB + b) * FF + f0_ + ah * 16);               \
            aReg[0] = ap[0]; aReg[1] = ap[1]; aReg[2] = ap[2]; aReg[3] = ap[3];   \
        } else {                                                                  \
            const uint4* hp = (const uint4*)(g_Xh +                               \
                (((size_t)m_ * NB + (n0 + ar)) * BB + b) * FF + f0_ + ah * 16);   \
            uint4 h0 = hp[0], h1 = hp[1];                                         \
            const __half2* u0 = (const __half2*)&h0;                              \
            const __half2* u1 = (const __half2*)&h1;                              \
            float2 f;                                                             \
            f = __half22float2(u0[0]); aReg[0].x = f.x; aReg[0].y = f.y;          \
            f = __half22float2(u0[1]); aReg[0].z = f.x; aReg[0].w = f.y;          \
            f = __half22float2(u0[2]); aReg[1].x = f.x; aReg[1].y = f.y;          \
            f = __half22float2(u0[3]); aReg[1].z = f.x; aReg[1].w = f.y;          \
            f = __half22float2(u1[0]); aReg[2].x = f.x; aReg[2].y = f.y;          \
            f = __half22float2(u1[1]); aReg[2].z = f.x; aReg[2].w = f.y;          \
            f = __half22float2(u1[2]); aReg[3].x = f.x; aReg[3].y = f.y;          \
            f = __half22float2(u1[3]); aReg[3].z = f.x; aReg[3].w = f.y;          \
        }                                                                         \
        const uint4* bh = (const uint4*)(g_Wth + ((size_t)m_ * OO + bo) * FF +    \
                                         f0_ + bp * 16);                          \
        const uint4* bl = (const uint4*)(g_Wtl + ((size_t)m_ * OO + bo) * FF +    \
                                         f0_ + bp * 16);                          \
        bRegH[0] = bh[0]; bRegH[1] = bh[1];                                       \
        bRegL[0] = bl[0]; bRegL[1] = bl[1];                                       \
    }

#define STS_TILE(st)                                                              \
    {                                                                             \
        uint16_t* Ah = smx + (st) * STG;                                          \
        uint16_t* Al = Ah + TSZ;                                                  \
        uint16_t* Bh = Ah + 2 * TSZ;                                              \
        uint16_t* Bl = Ah + 3 * TSZ;                                              \
        const float* av = (const float*)aReg;                                     \
        uint32_t* AhR = (uint32_t*)(Ah + ar * BKP + ah * 16);                     \
        uint32_t* AlR = (uint32_t*)(Al + ar * BKP + ah * 16);                     \
        _Pragma("unroll")                                                         \
        for (int j = 0; j < 8; j++) {                                             \
            float x0 = av[2 * j], x1 = av[2 * j + 1];                             \
            __nv_bfloat16 h0 = __float2bfloat16_rn(x0);                           \
            __nv_bfloat16 h1 = __float2bfloat16_rn(x1);                           \
            __nv_bfloat16 l0 = __float2bfloat16_rn(x0 - __bfloat162float(h0));    \
            __nv_bfloat16 l1 = __float2bfloat16_rn(x1 - __bfloat162float(h1));    \
            __nv_bfloat162 hp; hp.x = h0; hp.y = h1;                              \
            __nv_bfloat162 lp; lp.x = l0; lp.y = l1;                              \
            AhR[j] = *(uint32_t*)&hp;                                             \
            AlR[j] = *(uint32_t*)&lp;                                             \
        }                                                                         \
        uint32_t* BhR = (uint32_t*)(Bh + bo * BKP + bp * 16);                     \
        uint32_t* BlR = (uint32_t*)(Bl + bo * BKP + bp * 16);                     \
        const uint32_t* bhv = (const uint32_t*)bRegH;                             \
        const uint32_t* blv = (const uint32_t*)bRegL;                             \
        _Pragma("unroll")                                                         \
        for (int j = 0; j < 8; j++) { BhR[j] = bhv[j]; BlR[j] = blv[j]; }         \
    }

    LDG_TILE(0);
    STS_TILE(0);
    __syncthreads();

    for (int kt = 0; kt < 20; kt++) {
        const int st = kt & 1;
        if (kt < 19) LDG_TILE(kt + 1);

        const uint32_t baseAh = smem0 + (st * STG) * 2;
        const uint32_t baseAl = baseAh + TSZ * 2;
        const uint32_t baseBh = baseAh + 2 * TSZ * 2;
        const uint32_t baseBl = baseAh + 3 * TSZ * 2;

#pragma unroll
        for (int kk = 0; kk < BK; kk += 16) {
            uint32_t fbh[4][2], fbl[4][2];
#pragma unroll
            for (int p = 0; p < 2; p++) {
                uint32_t r[4];
                uint32_t off = (bRowOff + p * 16 * BKP + kk) * 2;
                ldsm_x4(r, baseBh + off);
                fbh[2 * p][0] = r[0]; fbh[2 * p][1] = r[1];
                fbh[2 * p + 1][0] = r[2]; fbh[2 * p + 1][1] = r[3];
                ldsm_x4(r, baseBl + off);
                fbl[2 * p][0] = r[0]; fbl[2 * p][1] = r[1];
                fbl[2 * p + 1][0] = r[2]; fbl[2 * p + 1][1] = r[3];
            }
#pragma unroll
            for (int mi = 0; mi < 4; mi++) {
                uint32_t fah[4], fal[4];
                uint32_t off = (aRowOff + mi * 16 * BKP + kk) * 2;
                ldsm_x4(fah, baseAh + off);
                ldsm_x4(fal, baseAl + off);
#pragma unroll
                for (int ni = 0; ni < 4; ni++) {
                    mma_bf16(acc[mi][ni], fah, fbh[ni]);
                    mma_bf16(acc[mi][ni], fah, fbl[ni]);
                    mma_bf16(acc[mi][ni], fal, fbh[ni]);
                }
            }
        }

        if (kt < 19) {
            STS_TILE(1 - st);
        }
        __syncthreads();
    }

#pragma unroll
    for (int mi = 0; mi < 4; mi++) {
#pragma unroll
        for (int ni = 0; ni < 4; ni++) {
            int col = wn * 32 + ni * 8 + 2 * qc;
            float b0 = biases[col], b1 = biases[col + 1];
            int r0 = bn0 + wm * 64 + mi * 16 + qr;
            float2 v0 = make_float2(acc[mi][ni][0] + b0, acc[mi][ni][1] + b1);
            float2 v1 = make_float2(acc[mi][ni][2] + b0, acc[mi][ni][3] + b1);
            *(float2*)(out + (size_t)r0 * OO + col)       = v0;
            *(float2*)(out + (size_t)(r0 + 8) * OO + col) = v1;
        }
    }
#undef LDG_TILE
#undef STS_TILE
}

// ---------------- launch ----------------
extern "C" void kernel_launch(void* const* d_in, const int* in_sizes, int n_in,
                              void* d_out, int out_size) {
    const float* inputs = (const float*)d_in[0];
    const float* state  = (const float*)d_in[1];
    const int*   rows   = (const int*)d_in[2];
    const int*   cols   = (const int*)d_in[3];
    const float* vals   = (const float*)d_in[4];
    const float* weight = (const float*)d_in[5];
    const float* biases = (const float*)d_in[6];
    float* out = (float*)d_out;
    (void)in_sizes; (void)n_in; (void)out_size;

    cudaFuncSetAttribute(k_gemm_mma, cudaFuncAttributeMaxDynamicSharedMemorySize,
                         GEMM_SMEM);

    k_zero_cnt<<<(SS * NB + 255) / 256, 256>>>();
    k_histo<<<(SS * EE) / 256, 256>>>(rows);
    k_scan<<<SS, 1024>>>();
    k_scatter<<<(SS * EE) / 256, 256>>>(rows, cols, vals);
    k_build<<<(NB * BB * 32) / 256, 256>>>((const float4*)inputs,
                                           (const float4*)state);
    k_wprep<<<(FF * OO) / 256, 256>>>(weight);
    k_spmm<<<dim3(NB, SS, 2), 256>>>(0);
    k_spmm<<<dim3(NB, SS, 2), 256>>>(1);
    k_gemm_mma<<<(BB * NB) / 128, 256, GEMM_SMEM>>>(biases, out);
}